// round 7
// baseline (speedup 1.0000x reference)
#include <cuda_runtime.h>
#include <math.h>

#define Bn   2048
#define Hn   64
#define An   32
#define Sn   32
#define Dn   200
#define OUTC 296
#define BT   16
#define NT   512

#define SR4  416   // padded stride for NOUT=400 (416*4B = 13*128B)
#define SR2  224   // padded stride for NOUT=200 (224*4B = 7*128B)

// ---------- persistent transposed weights (device globals, zero-padded) ----------
__device__ float g_Wru[272 * SR4];   // [K=272][416] fused r,u over [x;h]
__device__ float g_bru[400];
__device__ float g_Win[64 * SR2];    // i_n over x
__device__ float g_bin[200];
__device__ float g_Whn[208 * SR2];   // h_n over h
__device__ float g_bhn[200];
__device__ float g_W1t[208 * SR2];
__device__ float g_b1s[200];
__device__ float g_W2t[208 * SR2];
__device__ float g_b2s[200];
__device__ float g_Wms[208 * 64];    // heads: cols 0..31 mean, 32..63 logstd
__device__ float g_bms[64];

// ---------- packed fp32x2 helpers ----------
__device__ __forceinline__ unsigned long long fma2_(unsigned long long a,
                                                    unsigned long long b,
                                                    unsigned long long c) {
    unsigned long long d;
    asm("fma.rn.f32x2 %0, %1, %2, %3;" : "=l"(d) : "l"(a), "l"(b), "l"(c));
    return d;
}
__device__ __forceinline__ unsigned long long splat2_(float w) {
    unsigned long long d;
    asm("mov.b64 %0, {%1, %1};" : "=l"(d) : "f"(w));
    return d;
}
__device__ __forceinline__ void unpack2_(unsigned long long v, float& lo, float& hi) {
    asm("mov.b64 {%0, %1}, %2;" : "=f"(lo), "=f"(hi) : "l"(v));
}
__device__ __forceinline__ float sigf_(float x) { return 1.0f / (1.0f + __expf(-x)); }

// ---------- weight transpose / fuse (every launch; deterministic) ----------
__global__ void rssm_preproc(
    const float* __restrict__ W_ih, const float* __restrict__ b_ih,
    const float* __restrict__ W_hh, const float* __restrict__ b_hh,
    const float* __restrict__ W1,   const float* __restrict__ b1,
    const float* __restrict__ W2,   const float* __restrict__ b2,
    const float* __restrict__ Wm,   const float* __restrict__ bm,
    const float* __restrict__ Ws,   const float* __restrict__ bs)
{
    int i0 = blockIdx.x * blockDim.x + threadIdx.x;
    int stride = gridDim.x * blockDim.x;

    for (int idx = i0; idx < 272 * SR4; idx += stride) {
        int k = idx / SR4, o = idx % SR4;
        float v = 0.0f;
        if (o < 400) {
            if (k < 64) v = W_ih[o * 64 + k];
            else if (k < 264) v = W_hh[o * 200 + (k - 64)];
        }
        g_Wru[idx] = v;
    }
    for (int idx = i0; idx < 400; idx += stride) g_bru[idx] = b_ih[idx] + b_hh[idx];

    for (int idx = i0; idx < 64 * SR2; idx += stride) {
        int k = idx / SR2, o = idx % SR2;
        g_Win[idx] = (o < 200) ? W_ih[(400 + o) * 64 + k] : 0.0f;
    }
    for (int idx = i0; idx < 200; idx += stride) g_bin[idx] = b_ih[400 + idx];

    for (int idx = i0; idx < 208 * SR2; idx += stride) {
        int k = idx / SR2, o = idx % SR2;
        bool live = (k < 200) && (o < 200);
        g_Whn[idx] = live ? W_hh[(400 + o) * 200 + k] : 0.0f;
        g_W1t[idx] = live ? W1[o * 200 + k] : 0.0f;
        g_W2t[idx] = live ? W2[o * 200 + k] : 0.0f;
    }
    for (int idx = i0; idx < 200; idx += stride) {
        g_bhn[idx] = b_hh[400 + idx];
        g_b1s[idx] = b1[idx];
        g_b2s[idx] = b2[idx];
    }

    for (int idx = i0; idx < 208 * 64; idx += stride) {
        int k = idx / 64, o = idx % 64;
        float v = 0.0f;
        if (k < 200) v = (o < 32) ? Wm[o * 200 + k] : Ws[(o - 32) * 200 + k];
        g_Wms[idx] = v;
    }
    for (int idx = i0; idx < 64; idx += stride)
        g_bms[idx] = (idx < 32) ? bm[idx] : bs[idx - 32];
}

// ---------- col-pair GEMM unit: C=8 cols x RPT=4 rows per thread ----------
// outT[NOUT][16] (+)= Wt[K][SR] * xT[K][16]. t in [0, NOUT/2). K % 4 == 0.
// Weights read as native u64 col-pairs (no weight splats); x via LDS.128 + 4 splats.
template<int K, int NOUT, int SR, int BIAS, int ACT>
__device__ __forceinline__ void gemm8(const float* __restrict__ Wt,
                                      const float* __restrict__ bias,
                                      const float* __restrict__ xT,
                                      float* __restrict__ outT, int t)
{
    const int cg = t >> 2;        // column group (8 cols)
    const int rg = t & 3;         // row group (4 rows)
    const char* wp = (const char*)(Wt + cg * 8);
    const float* xp = xT + rg * 4;

    unsigned long long acc[4][4];
#pragma unroll
    for (int p = 0; p < 4; p++)
#pragma unroll
        for (int r = 0; r < 4; r++) acc[p][r] = 0ull;

    auto LD = [&](ulonglong2* b, int k0) {
        const char* base = wp + (size_t)k0 * (SR * 4);
        b[0] = __ldg((const ulonglong2*)(base));
        b[1] = __ldg((const ulonglong2*)(base + 16));
        b[2] = __ldg((const ulonglong2*)(base + SR * 4));
        b[3] = __ldg((const ulonglong2*)(base + SR * 4 + 16));
    };
    auto CP = [&](const ulonglong2* b, int k0) {
#pragma unroll
        for (int kk = 0; kk < 2; kk++) {
            float4 xv = *(const float4*)(xp + (k0 + kk) * BT);
            unsigned long long xs0 = splat2_(xv.x), xs1 = splat2_(xv.y);
            unsigned long long xs2 = splat2_(xv.z), xs3 = splat2_(xv.w);
            unsigned long long w01 = b[kk * 2].x, w23 = b[kk * 2].y;
            unsigned long long w45 = b[kk * 2 + 1].x, w67 = b[kk * 2 + 1].y;
            acc[0][0] = fma2_(w01, xs0, acc[0][0]);
            acc[1][0] = fma2_(w23, xs0, acc[1][0]);
            acc[2][0] = fma2_(w45, xs0, acc[2][0]);
            acc[3][0] = fma2_(w67, xs0, acc[3][0]);
            acc[0][1] = fma2_(w01, xs1, acc[0][1]);
            acc[1][1] = fma2_(w23, xs1, acc[1][1]);
            acc[2][1] = fma2_(w45, xs1, acc[2][1]);
            acc[3][1] = fma2_(w67, xs1, acc[3][1]);
            acc[0][2] = fma2_(w01, xs2, acc[0][2]);
            acc[1][2] = fma2_(w23, xs2, acc[1][2]);
            acc[2][2] = fma2_(w45, xs2, acc[2][2]);
            acc[3][2] = fma2_(w67, xs2, acc[3][2]);
            acc[0][3] = fma2_(w01, xs3, acc[0][3]);
            acc[1][3] = fma2_(w23, xs3, acc[1][3]);
            acc[2][3] = fma2_(w45, xs3, acc[2][3]);
            acc[3][3] = fma2_(w67, xs3, acc[3][3]);
        }
    };

    ulonglong2 bufA[4], bufB[4];
    LD(bufA, 0);
    for (int k0 = 0; k0 < K; k0 += 4) {
        LD(bufB, k0 + 2);
        CP(bufA, k0);
        if (k0 + 4 < K) LD(bufA, k0 + 4);
        CP(bufB, k0 + 2);
    }

#pragma unroll
    for (int p = 0; p < 4; p++) {
        int c0 = cg * 8 + 2 * p;
#pragma unroll
        for (int r = 0; r < 4; r++) {
            float lo, hi; unpack2_(acc[p][r], lo, hi);
            if (BIAS) { lo += bias[c0]; hi += bias[c0 + 1]; }
            if (ACT == 1) { lo = sigf_(lo); hi = sigf_(hi); }
            else if (ACT == 2) {
                lo = lo > 0.0f ? lo : (__expf(lo) - 1.0f);
                hi = hi > 0.0f ? hi : (__expf(hi) - 1.0f);
            }
            outT[c0 * BT + rg * 4 + r] = lo;
            outT[(c0 + 1) * BT + rg * 4 + r] = hi;
        }
    }
}

// ---------- main rollout kernel: 1 CTA = 16 batch rows, all 64 steps ----------
extern __shared__ float smf[];

#define OXH  0                   // [272][16]: z 0..31, a 32..63, h 64..263, pad
#define OEP  (OXH + 272*16)      // [32][16]
#define OPA  (OEP + 32*16)       // [400][16] K-split partials A
#define OPB  (OPA + 400*16)      // [400][16] K-split partials B
#define ONB1 (OPB + 400*16)      // [208][16] i_n -> f1
#define ONB2 (ONB1 + 208*16)     // [208][16] h_n -> f2
#define OHP  (ONB2 + 208*16)     // [8][64][16] head partials
#define OMS  (OHP + 8*64*16)     // [64][16] mean/std
#define SMEMF (OMS + 64*16)
#define SMEMB (SMEMF * 4)

__global__ void __launch_bounds__(NT, 1) rssm_main(
    const float* __restrict__ h0, const float* __restrict__ z0,
    const float* __restrict__ actions, const float* __restrict__ eps,
    float* __restrict__ out)
{
    float* xh  = smf + OXH;
    float* ep  = smf + OEP;
    float* pA  = smf + OPA;
    float* pB  = smf + OPB;
    float* nb1 = smf + ONB1;
    float* nb2 = smf + ONB2;
    float* hp  = smf + OHP;
    float* ms  = smf + OMS;

    const int tid = threadIdx.x;
    const int b0  = blockIdx.x * BT;

    // initial state + zero the K-padding rows (never rewritten)
    for (int idx = tid; idx < Dn * BT; idx += NT) {
        int f = idx >> 4, r = idx & 15;
        xh[64 * BT + idx] = h0[(b0 + r) * Dn + f];
    }
    for (int idx = tid; idx < Sn * BT; idx += NT) {
        int f = idx >> 4, r = idx & 15;
        xh[idx] = z0[(b0 + r) * Sn + f];
    }
    for (int idx = tid; idx < 8 * BT; idx += NT) {
        xh[264 * BT + idx] = 0.0f;
        nb1[200 * BT + idx] = 0.0f;
        nb2[200 * BT + idx] = 0.0f;
    }

    for (int t = 0; t < Hn; t++) {
        // stage actions[t], eps[t]
        for (int idx = tid; idx < An * BT; idx += NT) {
            int r = idx >> 5, c = idx & 31;
            size_t gbase = ((size_t)(b0 + r) * Hn + t);
            xh[(32 + c) * BT + r] = actions[gbase * An + c];
            ep[c * BT + r]        = eps[gbase * Sn + c];
        }
        __syncthreads();

        // Phase A: gates. 400-GEMM 2-way K-split + h_n + i_n, concurrent.
        if (tid < 200)
            gemm8<136, 400, SR4, 0, 0>(g_Wru, nullptr, xh, pA, tid);
        else if (tid < 400)
            gemm8<136, 400, SR4, 0, 0>(g_Wru + 136 * SR4, nullptr, xh + 136 * BT, pB, tid - 200);
        else if (tid < 500)
            gemm8<208, 200, SR2, 1, 0>(g_Whn, g_bhn, xh + 64 * BT, nb2, tid - 400);
        if (tid < 100)
            gemm8<64, 200, SR2, 1, 0>(g_Win, g_bin, xh, nb1, tid);
        __syncthreads();

        // GRU pointwise: reduce 400-GEMM K-split + gates + h update
        for (int idx = tid; idx < Dn * BT; idx += NT) {
            int f = idx >> 4;
            float rr = sigf_(pA[idx] + pB[idx] + g_bru[f]);
            float uu = sigf_(pA[3200 + idx] + pB[3200 + idx] + g_bru[200 + f]);
            float n  = tanhf(nb1[idx] + rr * nb2[idx]);
            float hv = xh[64 * BT + idx];
            xh[64 * BT + idx] = (1.0f - uu) * n + uu * hv;
        }
        __syncthreads();

        // Phase B: f1 = elu(W1 h + b1), 2-way K-split
        if (tid < 200)
            gemm8<104, 200, SR2, 0, 0>(g_W1t, nullptr, xh + 64 * BT, pA, tid);
        else if (tid < 400)
            gemm8<104, 200, SR2, 0, 0>(g_W1t + 104 * SR2, nullptr, xh + (64 + 104) * BT, pB, tid - 200);
        __syncthreads();
        for (int idx = tid; idx < Dn * BT; idx += NT) {
            int f = idx >> 4;
            float v = pA[idx] + pB[idx] + g_b1s[f];
            nb1[idx] = v > 0.0f ? v : (__expf(v) - 1.0f);
        }
        __syncthreads();

        // Phase C: f2 = elu(W2 f1 + b2), 2-way K-split
        if (tid < 200)
            gemm8<104, 200, SR2, 0, 0>(g_W2t, nullptr, nb1, pA, tid);
        else if (tid < 400)
            gemm8<104, 200, SR2, 0, 0>(g_W2t + 104 * SR2, nullptr, nb1 + 104 * BT, pB, tid - 200);
        __syncthreads();
        for (int idx = tid; idx < Dn * BT; idx += NT) {
            int f = idx >> 4;
            float v = pA[idx] + pB[idx] + g_b2s[f];
            nb2[idx] = v > 0.0f ? v : (__expf(v) - 1.0f);
        }
        __syncthreads();

        // heads (Nout=64, padded K=208), 8-way K-split of 26
        {
            int o = tid & 63, p = tid >> 6;
            const float* wp = g_Wms + p * 26 * 64 + o;
            const float* xb = nb2 + p * 26 * BT;
            unsigned long long acc[8];
#pragma unroll
            for (int q = 0; q < 8; q++) acc[q] = 0ull;
#pragma unroll
            for (int k = 0; k < 26; k += 2) {
                float w0 = __ldg(wp + k * 64);
                float w1 = __ldg(wp + (k + 1) * 64);
                unsigned long long wd0 = splat2_(w0), wd1 = splat2_(w1);
                const ulonglong2* x0 = reinterpret_cast<const ulonglong2*>(xb + k * BT);
                const ulonglong2* x1 = reinterpret_cast<const ulonglong2*>(xb + (k + 1) * BT);
#pragma unroll
                for (int q = 0; q < 4; q++) {
                    ulonglong2 a = x0[q], b = x1[q];
                    acc[2 * q]     = fma2_(wd0, a.x, acc[2 * q]);
                    acc[2 * q + 1] = fma2_(wd0, a.y, acc[2 * q + 1]);
                    acc[2 * q]     = fma2_(wd1, b.x, acc[2 * q]);
                    acc[2 * q + 1] = fma2_(wd1, b.y, acc[2 * q + 1]);
                }
            }
            float v[16];
#pragma unroll
            for (int q = 0; q < 8; q++) { unpack2_(acc[q], v[2 * q], v[2 * q + 1]); }
            float4* dp = reinterpret_cast<float4*>(hp + p * 1024 + o * BT);
#pragma unroll
            for (int q = 0; q < 4; q++)
                dp[q] = make_float4(v[4 * q], v[4 * q + 1], v[4 * q + 2], v[4 * q + 3]);
        }
        __syncthreads();

        // reduce head partials; mean raw, std = exp(clip(logstd))
        for (int idx = tid; idx < 1024; idx += NT) {
            int o = idx >> 4;
            float v = g_bms[o];
#pragma unroll
            for (int p = 0; p < 8; p++) v += hp[p * 1024 + idx];
            if (o < 32) ms[idx] = v;
            else        ms[idx] = __expf(fminf(fmaxf(v, -10.0f), 2.0f));
        }
        __syncthreads();

        // z_new = mean + std*eps
        for (int idx = tid; idx < Sn * BT; idx += NT)
            xh[idx] = ms[idx] + ms[512 + idx] * ep[idx];

        // emit outputs: [h(200) | z(32) | mean(32) | std(32)]
        for (int idx = tid; idx < OUTC * BT; idx += NT) {
            int r = idx / OUTC, c = idx - r * OUTC;
            float v;
            if (c < 200)       v = xh[64 * BT + c * BT + r];
            else if (c < 232) { int s = c - 200; v = ms[s * BT + r] + ms[(32 + s) * BT + r] * ep[s * BT + r]; }
            else               v = ms[(c - 232) * BT + r];
            out[((size_t)(b0 + r) * Hn + t) * OUTC + c] = v;
        }
        __syncthreads();
    }
}

// ---------- launch ----------
extern "C" void kernel_launch(void* const* d_in, const int* in_sizes, int n_in,
                              void* d_out, int out_size)
{
    const float* h0      = (const float*)d_in[0];
    const float* z0      = (const float*)d_in[1];
    const float* actions = (const float*)d_in[2];
    const float* eps_    = (const float*)d_in[3];
    const float* W_ih = (const float*)d_in[4];  const float* b_ih = (const float*)d_in[5];
    const float* W_hh = (const float*)d_in[6];  const float* b_hh = (const float*)d_in[7];
    const float* W1   = (const float*)d_in[8];  const float* b1   = (const float*)d_in[9];
    const float* W2   = (const float*)d_in[10]; const float* b2   = (const float*)d_in[11];
    const float* Wm   = (const float*)d_in[12]; const float* bm   = (const float*)d_in[13];
    const float* Ws   = (const float*)d_in[14]; const float* bs   = (const float*)d_in[15];
    float* out = (float*)d_out;

    cudaFuncSetAttribute(rssm_main, cudaFuncAttributeMaxDynamicSharedMemorySize, SMEMB);

    rssm_preproc<<<128, 256>>>(W_ih, b_ih, W_hh, b_hh, W1, b1, W2, b2, Wm, bm, Ws, bs);
    rssm_main<<<Bn / BT, NT, SMEMB>>>(h0, z0, actions, eps_, out);
}

// round 10
// speedup vs baseline: 1.2404x; 1.2404x over previous
#include <cuda_runtime.h>
#include <math.h>

#define Bn   2048
#define Hn   64
#define An   32
#define Sn   32
#define Dn   200
#define OUTC 296
#define BT   16
#define NT   256

#define SR4  416   // padded stride for NOUT=400 (416*4B = 13*128B)
#define SR2  224   // padded stride for NOUT=200 (224*4B = 7*128B)

// ---------- persistent transposed weights (device globals, zero-padded) ----------
__device__ float g_Wru[272 * SR4];   // [K=272][416] fused r,u over [x;h]
__device__ float g_bru[400];
__device__ float g_Win[64 * SR2];    // i_n over x
__device__ float g_bin[200];
__device__ float g_Whn[208 * SR2];   // h_n over h
__device__ float g_bhn[200];
__device__ float g_W1t[208 * SR2];
__device__ float g_b1s[200];
__device__ float g_W2t[208 * SR2];
__device__ float g_b2s[200];
__device__ float g_Wms[208 * 64];    // heads: cols 0..31 mean, 32..63 logstd
__device__ float g_bms[64];

// ---------- packed fp32x2 helpers ----------
__device__ __forceinline__ unsigned long long fma2_(unsigned long long a,
                                                    unsigned long long b,
                                                    unsigned long long c) {
    unsigned long long d;
    asm("fma.rn.f32x2 %0, %1, %2, %3;" : "=l"(d) : "l"(a), "l"(b), "l"(c));
    return d;
}
__device__ __forceinline__ unsigned long long splat2_(float w) {
    unsigned long long d;
    asm("mov.b64 %0, {%1, %1};" : "=l"(d) : "f"(w));
    return d;
}
__device__ __forceinline__ void unpack2_(unsigned long long v, float& lo, float& hi) {
    asm("mov.b64 {%0, %1}, %2;" : "=f"(lo), "=f"(hi) : "l"(v));
}
__device__ __forceinline__ float sigf_(float x) { return 1.0f / (1.0f + __expf(-x)); }

// ---------- weight transpose / fuse (every launch; deterministic) ----------
__global__ void rssm_preproc(
    const float* __restrict__ W_ih, const float* __restrict__ b_ih,
    const float* __restrict__ W_hh, const float* __restrict__ b_hh,
    const float* __restrict__ W1,   const float* __restrict__ b1,
    const float* __restrict__ W2,   const float* __restrict__ b2,
    const float* __restrict__ Wm,   const float* __restrict__ bm,
    const float* __restrict__ Ws,   const float* __restrict__ bs)
{
    int i0 = blockIdx.x * blockDim.x + threadIdx.x;
    int stride = gridDim.x * blockDim.x;

    for (int idx = i0; idx < 272 * SR4; idx += stride) {
        int k = idx / SR4, o = idx % SR4;
        float v = 0.0f;
        if (o < 400) {
            if (k < 64) v = W_ih[o * 64 + k];
            else if (k < 264) v = W_hh[o * 200 + (k - 64)];
        }
        g_Wru[idx] = v;
    }
    for (int idx = i0; idx < 400; idx += stride) g_bru[idx] = b_ih[idx] + b_hh[idx];

    for (int idx = i0; idx < 64 * SR2; idx += stride) {
        int k = idx / SR2, o = idx % SR2;
        g_Win[idx] = (o < 200) ? W_ih[(400 + o) * 64 + k] : 0.0f;
    }
    for (int idx = i0; idx < 200; idx += stride) g_bin[idx] = b_ih[400 + idx];

    for (int idx = i0; idx < 208 * SR2; idx += stride) {
        int k = idx / SR2, o = idx % SR2;
        bool live = (k < 200) && (o < 200);
        g_Whn[idx] = live ? W_hh[(400 + o) * 200 + k] : 0.0f;
        g_W1t[idx] = live ? W1[o * 200 + k] : 0.0f;
        g_W2t[idx] = live ? W2[o * 200 + k] : 0.0f;
    }
    for (int idx = i0; idx < 200; idx += stride) {
        g_bhn[idx] = b_hh[400 + idx];
        g_b1s[idx] = b1[idx];
        g_b2s[idx] = b2[idx];
    }

    for (int idx = i0; idx < 208 * 64; idx += stride) {
        int k = idx / 64, o = idx % 64;
        float v = 0.0f;
        if (k < 200) v = (o < 32) ? Wm[o * 200 + k] : Ws[(o - 32) * 200 + k];
        g_Wms[idx] = v;
    }
    for (int idx = i0; idx < 64; idx += stride)
        g_bms[idx] = (idx < 32) ? bm[idx] : bs[idx - 32];
}

// ---------- col-pair GEMM unit: C=8 cols x RPT=4 rows per thread ----------
// outT[NOUT][16] = Wt[K][SR] * xT[K][16] (+ bias, act). t in [0, NOUT/2). K % 4 == 0.
// Weights read as native u64 col-pairs (no weight splats); x via LDS.128 + 4 splats.
template<int K, int NOUT, int SR, int BIAS, int ACT>
__device__ __forceinline__ void gemm8(const float* __restrict__ Wt,
                                      const float* __restrict__ bias,
                                      const float* __restrict__ xT,
                                      float* __restrict__ outT, int t)
{
    const int cg = t >> 2;        // column group (8 cols)
    const int rg = t & 3;         // row group (4 rows)
    const char* wp = (const char*)(Wt + cg * 8);
    const float* xp = xT + rg * 4;

    unsigned long long acc[4][4];
#pragma unroll
    for (int p = 0; p < 4; p++)
#pragma unroll
        for (int r = 0; r < 4; r++) acc[p][r] = 0ull;

    auto LD = [&](ulonglong2* b, int k0) {
        const char* base = wp + (size_t)k0 * (SR * 4);
        b[0] = __ldg((const ulonglong2*)(base));
        b[1] = __ldg((const ulonglong2*)(base + 16));
        b[2] = __ldg((const ulonglong2*)(base + SR * 4));
        b[3] = __ldg((const ulonglong2*)(base + SR * 4 + 16));
    };
    auto CP = [&](const ulonglong2* b, int k0) {
#pragma unroll
        for (int kk = 0; kk < 2; kk++) {
            float4 xv = *(const float4*)(xp + (k0 + kk) * BT);
            unsigned long long xs0 = splat2_(xv.x), xs1 = splat2_(xv.y);
            unsigned long long xs2 = splat2_(xv.z), xs3 = splat2_(xv.w);
            unsigned long long w01 = b[kk * 2].x, w23 = b[kk * 2].y;
            unsigned long long w45 = b[kk * 2 + 1].x, w67 = b[kk * 2 + 1].y;
            acc[0][0] = fma2_(w01, xs0, acc[0][0]);
            acc[1][0] = fma2_(w23, xs0, acc[1][0]);
            acc[2][0] = fma2_(w45, xs0, acc[2][0]);
            acc[3][0] = fma2_(w67, xs0, acc[3][0]);
            acc[0][1] = fma2_(w01, xs1, acc[0][1]);
            acc[1][1] = fma2_(w23, xs1, acc[1][1]);
            acc[2][1] = fma2_(w45, xs1, acc[2][1]);
            acc[3][1] = fma2_(w67, xs1, acc[3][1]);
            acc[0][2] = fma2_(w01, xs2, acc[0][2]);
            acc[1][2] = fma2_(w23, xs2, acc[1][2]);
            acc[2][2] = fma2_(w45, xs2, acc[2][2]);
            acc[3][2] = fma2_(w67, xs2, acc[3][2]);
            acc[0][3] = fma2_(w01, xs3, acc[0][3]);
            acc[1][3] = fma2_(w23, xs3, acc[1][3]);
            acc[2][3] = fma2_(w45, xs3, acc[2][3]);
            acc[3][3] = fma2_(w67, xs3, acc[3][3]);
        }
    };

    ulonglong2 bufA[4], bufB[4];
    LD(bufA, 0);
    for (int k0 = 0; k0 < K; k0 += 4) {
        LD(bufB, k0 + 2);
        CP(bufA, k0);
        if (k0 + 4 < K) LD(bufA, k0 + 4);
        CP(bufB, k0 + 2);
    }

#pragma unroll
    for (int p = 0; p < 4; p++) {
        int c0 = cg * 8 + 2 * p;
#pragma unroll
        for (int r = 0; r < 4; r++) {
            float lo, hi; unpack2_(acc[p][r], lo, hi);
            if (BIAS) { lo += bias[c0]; hi += bias[c0 + 1]; }
            if (ACT == 1) { lo = sigf_(lo); hi = sigf_(hi); }
            else if (ACT == 2) {
                lo = lo > 0.0f ? lo : (__expf(lo) - 1.0f);
                hi = hi > 0.0f ? hi : (__expf(hi) - 1.0f);
            }
            outT[c0 * BT + rg * 4 + r] = lo;
            outT[(c0 + 1) * BT + rg * 4 + r] = hi;
        }
    }
}

// ---------- main rollout kernel: 1 CTA = 16 batch rows, all 64 steps ----------
extern __shared__ float smf[];

// SMEM float offsets
#define OXH  0                   // [272][16]: z 0..31, a 32..63, h 64..263, pad
#define OEP  (OXH + 272*16)      // [32][16]
#define ORU  (OEP + 32*16)       // [400][16] sigmoid(r,u); aliased by head partials
#define OHP  ORU                 // [4][64][16] head partials
#define OMS  (ORU + 400*16)      // [64][16] mean(0..31), std(32..63)
#define ONB1 (OMS + 64*16)       // [208][16] i_n -> f1
#define ONB2 (ONB1 + 208*16)     // [208][16] h_n -> f2
#define SMEMF (ONB2 + 208*16)
#define SMEMB (SMEMF * 4)

__global__ void __launch_bounds__(NT, 1) rssm_main(
    const float* __restrict__ h0, const float* __restrict__ z0,
    const float* __restrict__ actions, const float* __restrict__ eps,
    float* __restrict__ out)
{
    float* xh  = smf + OXH;
    float* ep  = smf + OEP;
    float* ru  = smf + ORU;
    float* hp  = smf + OHP;
    float* ms  = smf + OMS;
    float* nb1 = smf + ONB1;
    float* nb2 = smf + ONB2;

    const int tid = threadIdx.x;
    const int b0  = blockIdx.x * BT;

    // initial state + zero the K-padding rows (never rewritten afterwards)
    for (int idx = tid; idx < Dn * BT; idx += NT) {
        int f = idx >> 4, r = idx & 15;
        xh[64 * BT + idx] = h0[(b0 + r) * Dn + f];
    }
    for (int idx = tid; idx < Sn * BT; idx += NT) {
        int f = idx >> 4, r = idx & 15;
        xh[idx] = z0[(b0 + r) * Sn + f];
    }
    for (int idx = tid; idx < 8 * BT; idx += NT) {
        xh[264 * BT + idx] = 0.0f;
        nb1[200 * BT + idx] = 0.0f;
        nb2[200 * BT + idx] = 0.0f;
    }

    for (int t = 0; t < Hn; t++) {
        // stage actions[t], eps[t]
        for (int idx = tid; idx < An * BT; idx += NT) {
            int r = idx >> 5, c = idx & 31;
            size_t gbase = ((size_t)(b0 + r) * Hn + t);
            xh[(32 + c) * BT + r] = actions[gbase * An + c];
            ep[c * BT + r]        = eps[gbase * Sn + c];
        }
        __syncthreads();

        // Phase A: gates (no K-splits, full-K chains)
        if (tid < 200)
            gemm8<272, 400, SR4, 1, 1>(g_Wru, g_bru, xh, ru, tid);          // sigmoid(r,u)
        if (tid < 100)
            gemm8<208, 200, SR2, 1, 0>(g_Whn, g_bhn, xh + 64 * BT, nb2, tid);       // h_n
        else if (tid < 200)
            gemm8< 64, 200, SR2, 1, 0>(g_Win, g_bin, xh, nb1, tid - 100);           // i_n
        __syncthreads();

        // pointwise GRU update (in place on h region)
        for (int idx = tid; idx < Dn * BT; idx += NT) {
            float rr = ru[idx], u = ru[3200 + idx];
            float n  = tanhf(nb1[idx] + rr * nb2[idx]);
            float hv = xh[64 * BT + idx];
            xh[64 * BT + idx] = (1.0f - u) * n + u * hv;
        }
        __syncthreads();

        // f1 = elu(W1 h + b1)
        if (tid < 100)
            gemm8<208, 200, SR2, 1, 2>(g_W1t, g_b1s, xh + 64 * BT, nb1, tid);
        __syncthreads();
        // f2 = elu(W2 f1 + b2)
        if (tid < 100)
            gemm8<208, 200, SR2, 1, 2>(g_W2t, g_b2s, nb1, nb2, tid);
        __syncthreads();

        // heads (Nout=64, padded K=208), 4-way K-split of 52
        {
            int o = tid & 63, p = tid >> 6;
            const float* wp = g_Wms + p * 52 * 64 + o;
            const float* xb = nb2 + p * 52 * BT;
            unsigned long long acc[8];
#pragma unroll
            for (int q = 0; q < 8; q++) acc[q] = 0ull;
#pragma unroll 4
            for (int k = 0; k < 52; k += 2) {
                float w0 = __ldg(wp + k * 64);
                float w1 = __ldg(wp + (k + 1) * 64);
                unsigned long long wd0 = splat2_(w0), wd1 = splat2_(w1);
                const ulonglong2* x0 = reinterpret_cast<const ulonglong2*>(xb + k * BT);
                const ulonglong2* x1 = reinterpret_cast<const ulonglong2*>(xb + (k + 1) * BT);
#pragma unroll
                for (int q = 0; q < 4; q++) {
                    ulonglong2 a = x0[q], b = x1[q];
                    acc[2 * q]     = fma2_(wd0, a.x, acc[2 * q]);
                    acc[2 * q + 1] = fma2_(wd0, a.y, acc[2 * q + 1]);
                    acc[2 * q]     = fma2_(wd1, b.x, acc[2 * q]);
                    acc[2 * q + 1] = fma2_(wd1, b.y, acc[2 * q + 1]);
                }
            }
            float v[16];
#pragma unroll
            for (int q = 0; q < 8; q++) { unpack2_(acc[q], v[2 * q], v[2 * q + 1]); }
            float4* dp = reinterpret_cast<float4*>(hp + p * 1024 + o * BT);
#pragma unroll
            for (int q = 0; q < 4; q++)
                dp[q] = make_float4(v[4 * q], v[4 * q + 1], v[4 * q + 2], v[4 * q + 3]);
        }
        __syncthreads();

        // reduce K-split partials; mean raw, std = exp(clip(logstd))
        for (int idx = tid; idx < 1024; idx += NT) {
            int o = idx >> 4;
            float v = hp[idx] + hp[1024 + idx] + hp[2048 + idx] + hp[3072 + idx] + g_bms[o];
            if (o < 32) ms[idx] = v;
            else        ms[idx] = __expf(fminf(fmaxf(v, -10.0f), 2.0f));
        }
        __syncthreads();

        // z_new = mean + std*eps (state for next step)
        for (int idx = tid; idx < Sn * BT; idx += NT)
            xh[idx] = ms[idx] + ms[512 + idx] * ep[idx];

        // emit outputs: [h(200) | z(32) | mean(32) | std(32)]
        for (int idx = tid; idx < OUTC * BT; idx += NT) {
            int r = idx / OUTC, c = idx - r * OUTC;
            float v;
            if (c < 200)       v = xh[64 * BT + c * BT + r];
            else if (c < 232) { int s = c - 200; v = ms[s * BT + r] + ms[(32 + s) * BT + r] * ep[s * BT + r]; }
            else               v = ms[(c - 232) * BT + r];
            out[((size_t)(b0 + r) * Hn + t) * OUTC + c] = v;
        }
        __syncthreads();
    }
}

// ---------- launch ----------
extern "C" void kernel_launch(void* const* d_in, const int* in_sizes, int n_in,
                              void* d_out, int out_size)
{
    const float* h0      = (const float*)d_in[0];
    const float* z0      = (const float*)d_in[1];
    const float* actions = (const float*)d_in[2];
    const float* eps_    = (const float*)d_in[3];
    const float* W_ih = (const float*)d_in[4];  const float* b_ih = (const float*)d_in[5];
    const float* W_hh = (const float*)d_in[6];  const float* b_hh = (const float*)d_in[7];
    const float* W1   = (const float*)d_in[8];  const float* b1   = (const float*)d_in[9];
    const float* W2   = (const float*)d_in[10]; const float* b2   = (const float*)d_in[11];
    const float* Wm   = (const float*)d_in[12]; const float* bm   = (const float*)d_in[13];
    const float* Ws   = (const float*)d_in[14]; const float* bs   = (const float*)d_in[15];
    float* out = (float*)d_out;

    cudaFuncSetAttribute(rssm_main, cudaFuncAttributeMaxDynamicSharedMemorySize, SMEMB);

    rssm_preproc<<<128, 256>>>(W_ih, b_ih, W_hh, b_hh, W1, b1, W2, b2, Wm, bm, Ws, bs);
    rssm_main<<<Bn / BT, NT, SMEMB>>>(h0, z0, actions, eps_, out);
}

// round 12
// speedup vs baseline: 1.5078x; 1.2156x over previous
#include <cuda_runtime.h>
#include <math.h>

#define Bn   2048
#define Hn   64
#define An   32
#define Sn   32
#define Dn   200
#define OUTC 296
#define BT   16
#define NT   256

#define SR4  416   // padded stride for NOUT=400
#define SR2  224   // padded stride for NOUT=200

// ---------- persistent transposed weights (device globals, zero-padded) ----------
__device__ float g_Wru[272 * SR4];   // [K=272][416] fused r,u over [x;h]
__device__ float g_bru[400];
__device__ float g_Win[64 * SR2];    // i_n over x
__device__ float g_bin[200];
__device__ float g_Whn[208 * SR2];   // h_n over h
__device__ float g_bhn[200];
__device__ float g_W1t[208 * SR2];
__device__ float g_b1s[200];
__device__ float g_W2t[208 * SR2];
__device__ float g_b2s[200];
__device__ float g_Wms[208 * 64];    // heads: cols 0..31 mean, 32..63 logstd
__device__ float g_bms[64];

// ---------- packed fp32x2 helpers ----------
__device__ __forceinline__ unsigned long long fma2_(unsigned long long a,
                                                    unsigned long long b,
                                                    unsigned long long c) {
    unsigned long long d;
    asm("fma.rn.f32x2 %0, %1, %2, %3;" : "=l"(d) : "l"(a), "l"(b), "l"(c));
    return d;
}
__device__ __forceinline__ unsigned long long splat2_(float w) {
    unsigned long long d;
    asm("mov.b64 %0, {%1, %1};" : "=l"(d) : "f"(w));
    return d;
}
__device__ __forceinline__ void unpack2_(unsigned long long v, float& lo, float& hi) {
    asm("mov.b64 {%0, %1}, %2;" : "=f"(lo), "=f"(hi) : "l"(v));
}
__device__ __forceinline__ float sigf_(float x) { return 1.0f / (1.0f + __expf(-x)); }

// ---------- weight transpose / fuse (every launch; deterministic) ----------
__global__ void rssm_preproc(
    const float* __restrict__ W_ih, const float* __restrict__ b_ih,
    const float* __restrict__ W_hh, const float* __restrict__ b_hh,
    const float* __restrict__ W1,   const float* __restrict__ b1,
    const float* __restrict__ W2,   const float* __restrict__ b2,
    const float* __restrict__ Wm,   const float* __restrict__ bm,
    const float* __restrict__ Ws,   const float* __restrict__ bs)
{
    int i0 = blockIdx.x * blockDim.x + threadIdx.x;
    int stride = gridDim.x * blockDim.x;

    for (int idx = i0; idx < 272 * SR4; idx += stride) {
        int k = idx / SR4, o = idx % SR4;
        float v = 0.0f;
        if (o < 400) {
            if (k < 64) v = W_ih[o * 64 + k];
            else if (k < 264) v = W_hh[o * 200 + (k - 64)];
        }
        g_Wru[idx] = v;
    }
    for (int idx = i0; idx < 400; idx += stride) g_bru[idx] = b_ih[idx] + b_hh[idx];

    for (int idx = i0; idx < 64 * SR2; idx += stride) {
        int k = idx / SR2, o = idx % SR2;
        g_Win[idx] = (o < 200) ? W_ih[(400 + o) * 64 + k] : 0.0f;
    }
    for (int idx = i0; idx < 200; idx += stride) g_bin[idx] = b_ih[400 + idx];

    for (int idx = i0; idx < 208 * SR2; idx += stride) {
        int k = idx / SR2, o = idx % SR2;
        bool live = (k < 200) && (o < 200);
        g_Whn[idx] = live ? W_hh[(400 + o) * 200 + k] : 0.0f;
        g_W1t[idx] = live ? W1[o * 200 + k] : 0.0f;
        g_W2t[idx] = live ? W2[o * 200 + k] : 0.0f;
    }
    for (int idx = i0; idx < 200; idx += stride) {
        g_bhn[idx] = b_hh[400 + idx];
        g_b1s[idx] = b1[idx];
        g_b2s[idx] = b2[idx];
    }

    for (int idx = i0; idx < 208 * 64; idx += stride) {
        int k = idx / 64, o = idx % 64;
        float v = 0.0f;
        if (k < 200) v = (o < 32) ? Wm[o * 200 + k] : Ws[(o - 32) * 200 + k];
        g_Wms[idx] = v;
    }
    for (int idx = i0; idx < 64; idx += stride)
        g_bms[idx] = (idx < 32) ? bm[idx] : bs[idx - 32];
}

// ---------- gemm4: C=4 cols x 8 rows (RG=2), LDG.128 weights, depth-8 prefetch ----
// threads used: NOUT/2. K % 16 == 0. ACT: 1=sigmoid.
template<int K, int NOUT, int SR, int ACT>
__device__ __forceinline__ void gemm4(const float* __restrict__ Wt,
                                      const float* __restrict__ bias,
                                      const float* __restrict__ xT,
                                      float* __restrict__ outT, int t)
{
    const int cg = t >> 1, rg = t & 1;
    const float* wp = Wt + cg * 4;
    const float* xb = xT + rg * 8;

    unsigned long long acc[4][4];
#pragma unroll
    for (int ci = 0; ci < 4; ci++)
#pragma unroll
        for (int q = 0; q < 4; q++) acc[ci][q] = 0ull;

    auto LD = [&](float4* b, int k0) {
#pragma unroll
        for (int p = 0; p < 8; p++)
            b[p] = __ldg(reinterpret_cast<const float4*>(wp + (size_t)(k0 + p) * SR));
    };
    auto CP = [&](const float4* b, int k0) {
#pragma unroll
        for (int p = 0; p < 8; p++) {
            int k = k0 + p;
            ulonglong2 xa = *reinterpret_cast<const ulonglong2*>(xb + k * BT);
            ulonglong2 xc = *reinterpret_cast<const ulonglong2*>(xb + k * BT + 4);
            unsigned long long xv[4] = {xa.x, xa.y, xc.x, xc.y};
            float w[4] = {b[p].x, b[p].y, b[p].z, b[p].w};
#pragma unroll
            for (int ci = 0; ci < 4; ci++) {
                unsigned long long wd = splat2_(w[ci]);
#pragma unroll
                for (int q = 0; q < 4; q++)
                    acc[ci][q] = fma2_(wd, xv[q], acc[ci][q]);
            }
        }
    };

    float4 bufA[8], bufB[8];
    LD(bufA, 0);
    for (int k0 = 0; k0 < K; k0 += 16) {
        LD(bufB, k0 + 8);
        CP(bufA, k0);
        if (k0 + 16 < K) LD(bufA, k0 + 16);
        CP(bufB, k0 + 8);
    }

#pragma unroll
    for (int ci = 0; ci < 4; ci++) {
        int c = cg * 4 + ci;
        float bv = bias[c];
#pragma unroll
        for (int q = 0; q < 4; q++) {
            float lo, hi; unpack2_(acc[ci][q], lo, hi);
            lo += bv; hi += bv;
            if (ACT == 1) { lo = sigf_(lo); hi = sigf_(hi); }
            outT[c * BT + rg * 8 + 2 * q]     = lo;
            outT[c * BT + rg * 8 + 2 * q + 1] = hi;
        }
    }
}

// ---------- gemm2: C=2 cols x 8 rows (RG=2), LDG.64 weights, depth-8 prefetch ----
// threads used: NOUT. K % 16 == 0. ACT: 0=none, 2=elu.
template<int K, int NOUT, int SR, int ACT>
__device__ __forceinline__ void gemm2(const float* __restrict__ Wt,
                                      const float* __restrict__ bias,
                                      const float* __restrict__ xT,
                                      float* __restrict__ outT, int t)
{
    const int cg = t >> 1, rg = t & 1;
    const float* wp = Wt + cg * 2;
    const float* xb = xT + rg * 8;

    unsigned long long acc[2][4];
#pragma unroll
    for (int ci = 0; ci < 2; ci++)
#pragma unroll
        for (int q = 0; q < 4; q++) acc[ci][q] = 0ull;

    auto LD = [&](float2* b, int k0) {
#pragma unroll
        for (int p = 0; p < 8; p++)
            b[p] = __ldg(reinterpret_cast<const float2*>(wp + (size_t)(k0 + p) * SR));
    };
    auto CP = [&](const float2* b, int k0) {
#pragma unroll
        for (int p = 0; p < 8; p++) {
            int k = k0 + p;
            ulonglong2 xa = *reinterpret_cast<const ulonglong2*>(xb + k * BT);
            ulonglong2 xc = *reinterpret_cast<const ulonglong2*>(xb + k * BT + 4);
            unsigned long long w0 = splat2_(b[p].x), w1 = splat2_(b[p].y);
            acc[0][0] = fma2_(w0, xa.x, acc[0][0]);
            acc[0][1] = fma2_(w0, xa.y, acc[0][1]);
            acc[0][2] = fma2_(w0, xc.x, acc[0][2]);
            acc[0][3] = fma2_(w0, xc.y, acc[0][3]);
            acc[1][0] = fma2_(w1, xa.x, acc[1][0]);
            acc[1][1] = fma2_(w1, xa.y, acc[1][1]);
            acc[1][2] = fma2_(w1, xc.x, acc[1][2]);
            acc[1][3] = fma2_(w1, xc.y, acc[1][3]);
        }
    };

    float2 bufA[8], bufB[8];
    LD(bufA, 0);
    for (int k0 = 0; k0 < K; k0 += 16) {
        LD(bufB, k0 + 8);
        CP(bufA, k0);
        if (k0 + 16 < K) LD(bufA, k0 + 16);
        CP(bufB, k0 + 8);
    }

#pragma unroll
    for (int ci = 0; ci < 2; ci++) {
        int c = cg * 2 + ci;
        float bv = bias[c];
#pragma unroll
        for (int q = 0; q < 4; q++) {
            float lo, hi; unpack2_(acc[ci][q], lo, hi);
            lo += bv; hi += bv;
            if (ACT == 2) {
                lo = lo > 0.0f ? lo : (__expf(lo) - 1.0f);
                hi = hi > 0.0f ? hi : (__expf(hi) - 1.0f);
            }
            outT[c * BT + rg * 8 + 2 * q]     = lo;
            outT[c * BT + rg * 8 + 2 * q + 1] = hi;
        }
    }
}

// ---------- main rollout kernel: 1 CTA = 16 batch rows, all 64 steps ----------
extern __shared__ float smf[];

// SMEM float offsets
#define OXH  0                   // [272][16]: z 0..31, a 32..63, h 64..263, pad
#define OEP  (OXH + 272*16)      // 2 x [32][16] double-buffered eps
#define ORU  (OEP + 2*32*16)     // [400][16] sigmoid(r,u); aliased by head partials
#define OHP  ORU                 // [4][64][16] head partials
#define OMS  (ORU + 400*16)      // [64][16] mean(0..31), std(32..63)
#define ONB1 (OMS + 64*16)       // [208][16] i_n -> f1
#define ONB2 (ONB1 + 208*16)     // [208][16] h_n -> f2
#define SMEMF (ONB2 + 208*16)
#define SMEMB (SMEMF * 4)

__global__ void __launch_bounds__(NT, 1) rssm_main(
    const float* __restrict__ h0, const float* __restrict__ z0,
    const float* __restrict__ actions, const float* __restrict__ eps,
    float* __restrict__ out)
{
    float* xh  = smf + OXH;
    float* ep  = smf + OEP;   // ep + (t&1)*512
    float* ru  = smf + ORU;
    float* hp  = smf + OHP;
    float* ms  = smf + OMS;
    float* nb1 = smf + ONB1;
    float* nb2 = smf + ONB2;

    const int tid = threadIdx.x;
    const int b0  = blockIdx.x * BT;

    // emit step tq (reads xh-h, xh-z, ms; all stable during next step's phase A)
    auto emit_step = [&](int tq, int i0, int istep) {
        for (int idx = i0; idx < OUTC * BT; idx += istep) {
            int r = idx / OUTC, c = idx - r * OUTC;
            float v;
            if (c < 200)      v = xh[64 * BT + c * BT + r];
            else if (c < 232) v = xh[(c - 200) * BT + r];
            else              v = ms[(c - 232) * BT + r];
            out[((size_t)(b0 + r) * Hn + tq) * OUTC + c] = v;
        }
    };
    // stage actions[tq] into xh-a and eps[tq] into ep buffer (tq&1)
    auto stage = [&](int tq, int i0, int istep) {
        float* epb = ep + (tq & 1) * 512;
        for (int idx = i0; idx < An * BT; idx += istep) {
            int r = idx >> 5, c = idx & 31;
            size_t gbase = ((size_t)(b0 + r) * Hn + tq);
            xh[(32 + c) * BT + r] = actions[gbase * An + c];
            epb[c * BT + r]       = eps[gbase * Sn + c];
        }
    };

    // initial state + zero K-pad rows (never rewritten afterwards)
    for (int idx = tid; idx < Dn * BT; idx += NT) {
        int f = idx >> 4, r = idx & 15;
        xh[64 * BT + idx] = h0[(b0 + r) * Dn + f];
    }
    for (int idx = tid; idx < Sn * BT; idx += NT) {
        int f = idx >> 4, r = idx & 15;
        xh[idx] = z0[(b0 + r) * Sn + f];
    }
    for (int idx = tid; idx < 8 * BT; idx += NT) {
        xh[264 * BT + idx] = 0.0f;
        nb1[200 * BT + idx] = 0.0f;
        nb2[200 * BT + idx] = 0.0f;
    }
    stage(0, tid, NT);
    __syncthreads();

    for (int t = 0; t < Hn; t++) {
        // ---- Phase A: gate GEMMs on tid<200; emit(t-1) on tid>=200 ----
        if (tid < 200) {
            gemm4<272, 400, SR4, 1>(g_Wru, g_bru, xh, ru, tid);            // sigmoid(r,u)
            gemm2<208, 200, SR2, 0>(g_Whn, g_bhn, xh + 64 * BT, nb2, tid); // h_n
            gemm2< 64, 200, SR2, 0>(g_Win, g_bin, xh, nb1, tid);           // i_n
        } else if (t > 0) {
            emit_step(t - 1, tid - 200, NT - 200);
        }
        __syncthreads();

        // ---- Phase B: pointwise GRU update (all threads, in place on h) ----
        for (int idx = tid; idx < Dn * BT; idx += NT) {
            float rr = ru[idx], u = ru[3200 + idx];
            float n  = tanhf(nb1[idx] + rr * nb2[idx]);
            float hv = xh[64 * BT + idx];
            xh[64 * BT + idx] = (1.0f - u) * n + u * hv;
        }
        __syncthreads();

        // ---- Phase C: f1 on tid<200; stage(t+1) on tid>=200 ----
        if (tid < 200)
            gemm2<208, 200, SR2, 2>(g_W1t, g_b1s, xh + 64 * BT, nb1, tid);
        else if (t + 1 < Hn)
            stage(t + 1, tid - 200, NT - 200);
        __syncthreads();

        // ---- Phase D: f2 ----
        if (tid < 200)
            gemm2<208, 200, SR2, 2>(g_W2t, g_b2s, nb1, nb2, tid);
        __syncthreads();

        // ---- Phase E: heads (Nout=64, padded K=208), 4-way K-split of 52 ----
        {
            int o = tid & 63, p = tid >> 6;
            const float* wp = g_Wms + p * 52 * 64 + o;
            const float* xb = nb2 + p * 52 * BT;
            unsigned long long acc[8];
#pragma unroll
            for (int q = 0; q < 8; q++) acc[q] = 0ull;
#pragma unroll 4
            for (int k = 0; k < 52; k += 2) {
                float w0 = __ldg(wp + k * 64);
                float w1 = __ldg(wp + (k + 1) * 64);
                unsigned long long wd0 = splat2_(w0), wd1 = splat2_(w1);
                const ulonglong2* x0 = reinterpret_cast<const ulonglong2*>(xb + k * BT);
                const ulonglong2* x1 = reinterpret_cast<const ulonglong2*>(xb + (k + 1) * BT);
#pragma unroll
                for (int q = 0; q < 4; q++) {
                    ulonglong2 a = x0[q], b = x1[q];
                    acc[2 * q]     = fma2_(wd0, a.x, acc[2 * q]);
                    acc[2 * q + 1] = fma2_(wd0, a.y, acc[2 * q + 1]);
                    acc[2 * q]     = fma2_(wd1, b.x, acc[2 * q]);
                    acc[2 * q + 1] = fma2_(wd1, b.y, acc[2 * q + 1]);
                }
            }
            float v[16];
#pragma unroll
            for (int q = 0; q < 8; q++) { unpack2_(acc[q], v[2 * q], v[2 * q + 1]); }
            float4* dp = reinterpret_cast<float4*>(hp + p * 1024 + o * BT);
#pragma unroll
            for (int q = 0; q < 4; q++)
                dp[q] = make_float4(v[4 * q], v[4 * q + 1], v[4 * q + 2], v[4 * q + 3]);
        }
        __syncthreads();

        // ---- Phase F: reduce head partials; mean raw, std = exp(clip) ----
        for (int idx = tid; idx < 1024; idx += NT) {
            int o = idx >> 4;
            float v = hp[idx] + hp[1024 + idx] + hp[2048 + idx] + hp[3072 + idx] + g_bms[o];
            if (o < 32) ms[idx] = v;
            else        ms[idx] = __expf(fminf(fmaxf(v, -10.0f), 2.0f));
        }
        __syncthreads();

        // ---- Phase G: z_new = mean + std*eps ----
        {
            const float* epc = ep + (t & 1) * 512;
            for (int idx = tid; idx < Sn * BT; idx += NT)
                xh[idx] = ms[idx] + ms[512 + idx] * epc[idx];
        }
        __syncthreads();
    }

    // final emit (step Hn-1), all threads
    emit_step(Hn - 1, tid, NT);
}

// ---------- launch ----------
extern "C" void kernel_launch(void* const* d_in, const int* in_sizes, int n_in,
                              void* d_out, int out_size)
{
    const float* h0      = (const float*)d_in[0];
    const float* z0      = (const float*)d_in[1];
    const float* actions = (const float*)d_in[2];
    const float* eps_    = (const float*)d_in[3];
    const float* W_ih = (const float*)d_in[4];  const float* b_ih = (const float*)d_in[5];
    const float* W_hh = (const float*)d_in[6];  const float* b_hh = (const float*)d_in[7];
    const float* W1   = (const float*)d_in[8];  const float* b1   = (const float*)d_in[9];
    const float* W2   = (const float*)d_in[10]; const float* b2   = (const float*)d_in[11];
    const float* Wm   = (const float*)d_in[12]; const float* bm   = (const float*)d_in[13];
    const float* Ws   = (const float*)d_in[14]; const float* bs   = (const float*)d_in[15];
    float* out = (float*)d_out;

    cudaFuncSetAttribute(rssm_main, cudaFuncAttributeMaxDynamicSharedMemorySize, SMEMB);

    rssm_preproc<<<128, 256>>>(W_ih, b_ih, W_hh, b_hh, W1, b1, W2, b2, Wm, bm, Ws, bs);
    rssm_main<<<Bn / BT, NT, SMEMB>>>(h0, z0, actions, eps_, out);
}